// round 15
// baseline (speedup 1.0000x reference)
#include <cuda_runtime.h>
#include <cuda_bf16.h>
#include <cuda_fp16.h>
#include <cstdint>

// B=128, C=512, H=W=14, WIN=7, SHIFT=3, HEADS=16, HD=32, HID=2048
static constexpr int MT = 25088;  // B*H*W = B*nW*N

// ---- scratch (__device__ globals: allocation-free kernel_launch) ----
__device__ __align__(16) uint8_t       g_XW [(size_t)MT * 512];   // LN1 tokens, e4m3
__device__ __align__(16) float         g_XT [(size_t)MT * 512];   // x fp32 token-major
__device__ __align__(16) uint8_t       g_QK [(size_t)MT * 1024];  // q(0..511), k(512..1023) e4m3
__device__ __align__(16) __nv_bfloat16 g_V  [(size_t)MT * 512];   // v bf16
__device__ __align__(16) uint8_t       g_ATT[(size_t)MT * 512];   // e4m3
__device__ __align__(16) float         g_X1 [(size_t)MT * 512];   // running residual fp32
__device__ __align__(16) uint8_t       g_Z  [(size_t)MT * 512];   // e4m3
__device__ __align__(16) uint8_t       g_HB [(size_t)MT * 2048];  // e4m3
__device__ __align__(16) uint8_t g_QKVW[1536 * 512];
__device__ __align__(16) uint8_t g_PROJW[512 * 512];
__device__ __align__(16) uint8_t g_FC1W[2048 * 512];
__device__ __align__(16) uint8_t g_FC2W[512 * 2048];
__device__ float g_QKVB[1536];
__device__ __align__(4) __half g_BM[64 * 49 * 50];  // [wl][head] bias+mask, fp16, stride-50 rows

// ---- PTX helpers ----
__device__ __forceinline__ void cp16(void* sm, const void* gm) {
    uint32_t s = (uint32_t)__cvta_generic_to_shared(sm);
    asm volatile("cp.async.cg.shared.global [%0], [%1], 16;\n" :: "r"(s), "l"(gm));
}
__device__ __forceinline__ void ldm4(uint32_t r[4], const void* p) {
    uint32_t a = (uint32_t)__cvta_generic_to_shared(p);
    asm volatile("ldmatrix.sync.aligned.m8n8.x4.shared.b16 {%0,%1,%2,%3}, [%4];\n"
                 : "=r"(r[0]), "=r"(r[1]), "=r"(r[2]), "=r"(r[3]) : "r"(a));
}
__device__ __forceinline__ void ldm4t(uint32_t r[4], const void* p) {
    uint32_t a = (uint32_t)__cvta_generic_to_shared(p);
    asm volatile("ldmatrix.sync.aligned.m8n8.x4.trans.shared.b16 {%0,%1,%2,%3}, [%4];\n"
                 : "=r"(r[0]), "=r"(r[1]), "=r"(r[2]), "=r"(r[3]) : "r"(a));
}
__device__ __forceinline__ void mma_bf16(float c[4], const uint32_t a[4], const uint32_t b[2]) {
    asm volatile("mma.sync.aligned.m16n8k16.row.col.f32.bf16.bf16.f32 "
                 "{%0,%1,%2,%3}, {%4,%5,%6,%7}, {%8,%9}, {%0,%1,%2,%3};\n"
                 : "+f"(c[0]), "+f"(c[1]), "+f"(c[2]), "+f"(c[3])
                 : "r"(a[0]), "r"(a[1]), "r"(a[2]), "r"(a[3]), "r"(b[0]), "r"(b[1]));
}
__device__ __forceinline__ void mma_fp8(float c[4], const uint32_t a[4], const uint32_t b[2]) {
    asm volatile("mma.sync.aligned.m16n8k32.row.col.f32.e4m3.e4m3.f32 "
                 "{%0,%1,%2,%3}, {%4,%5,%6,%7}, {%8,%9}, {%0,%1,%2,%3};\n"
                 : "+f"(c[0]), "+f"(c[1]), "+f"(c[2]), "+f"(c[3])
                 : "r"(a[0]), "r"(a[1]), "r"(a[2]), "r"(a[3]), "r"(b[0]), "r"(b[1]));
}
// f16-accumulate fp8 mma (halves accumulator registers)
__device__ __forceinline__ void mma_fp8h(uint32_t c[2], const uint32_t a[4], const uint32_t b[2]) {
    asm volatile("mma.sync.aligned.m16n8k32.row.col.f16.e4m3.e4m3.f16 "
                 "{%0,%1}, {%2,%3,%4,%5}, {%6,%7}, {%0,%1};\n"
                 : "+r"(c[0]), "+r"(c[1])
                 : "r"(a[0]), "r"(a[1]), "r"(a[2]), "r"(a[3]), "r"(b[0]), "r"(b[1]));
}
__device__ __forceinline__ uint32_t packbf(float a, float b) {
    __nv_bfloat162 t = __floats2bfloat162_rn(a, b);
    return *reinterpret_cast<uint32_t*>(&t);
}
__device__ __forceinline__ uint16_t pack8(float lo, float hi) {
    uint16_t r;
    asm("cvt.rn.satfinite.e4m3x2.f32 %0, %1, %2;" : "=h"(r) : "f"(hi), "f"(lo));
    return r;
}
__device__ __forceinline__ uint8_t fp8(float v) {
    return (uint8_t)(pack8(v, 0.f) & 0xFF);
}

// ---- prep: weights -> e4m3 vectorized, bias/mask tables (fp16), qkv bias ----
static constexpr int EW_ELEM = 512 * 6144;
static constexpr int W4 = EW_ELEM / 4;
__global__ void prep_kernel(const float* __restrict__ qkvw, const float* __restrict__ projw,
                            const float* __restrict__ fc1w, const float* __restrict__ fc2w,
                            const float* __restrict__ rel_bias, const float* __restrict__ qkvb) {
    int t = blockIdx.x * 256 + threadIdx.x;
    const int E0 = 1536 * 512, E1 = 512 * 512, E2 = 2048 * 512;
    if (t < W4) {
        int i = t * 4;
        float4 v;
        uint8_t* dst;
        if (i < E0) {
            v = *reinterpret_cast<const float4*>(qkvw + i);
            if (i < 512 * 512) {
                v.x *= 0.17677669529663687f; v.y *= 0.17677669529663687f;
                v.z *= 0.17677669529663687f; v.w *= 0.17677669529663687f;
            }
            dst = g_QKVW + i;
        } else if (i < E0 + E1) {
            v = *reinterpret_cast<const float4*>(projw + (i - E0));
            dst = g_PROJW + (i - E0);
        } else if (i < E0 + E1 + E2) {
            v = *reinterpret_cast<const float4*>(fc1w + (i - E0 - E1));
            dst = g_FC1W + (i - E0 - E1);
        } else {
            v = *reinterpret_cast<const float4*>(fc2w + (i - E0 - E1 - E2));
            dst = g_FC2W + (i - E0 - E1 - E2);
        }
        *reinterpret_cast<uint32_t*>(dst) =
            (uint32_t)pack8(v.x, v.y) | ((uint32_t)pack8(v.z, v.w) << 16);
    } else if (t < W4 + 64 * 2450) {
        int j = t - W4;
        int combo = j / 2450, e = j - combo * 2450;
        int wl = combo >> 4, head = combo & 15;
        int a = e / 50, b = e - a * 50;
        float v = 0.f;
        if (b < 49) {
            int ra = a / 7, ca = a - ra * 7, rb = b / 7, cb = b - rb * 7;
            v = rel_bias[((ra - rb + 6) * 13 + (ca - cb + 6)) * 16 + head];
            int wh = wl >> 1, ww = wl & 1;
            int ha = wh * 7 + ra, wa = ww * 7 + ca;
            int hb = wh * 7 + rb, wb = ww * 7 + cb;
            int ga = (ha < 7 ? 0 : (ha < 11 ? 1 : 2)) * 3 + (wa < 7 ? 0 : (wa < 11 ? 1 : 2));
            int gb = (hb < 7 ? 0 : (hb < 11 ? 1 : 2)) * 3 + (wb < 7 ? 0 : (wb < 11 ? 1 : 2));
            if (ga != gb) v -= 100.f;
        }
        g_BM[j] = __float2half(v);
    } else if (t < W4 + 64 * 2450 + 1536) {
        int j = t - W4 - 64 * 2450;
        g_QKVB[j] = qkvb[j] * (j < 512 ? 0.17677669529663687f : 1.f);
    }
}

// ---- LN1: x(NCHW) -> g_XW e4m3 tokens (roll + window partition) AND g_XT fp32 copy ----
__global__ __launch_bounds__(256)
void ln1_kernel(const float* __restrict__ xin, const float* __restrict__ w,
                const float* __restrict__ bns) {
    __shared__ float tile[512 * 15];
    __shared__ float smu[14], srs[14];
    const int bb = blockIdx.x / 14, h = blockIdx.x - bb * 14;
    const float* xp = xin + (size_t)bb * 100352 + h * 14;
    const int tid = threadIdx.x;

    for (int idx = tid; idx < 512 * 14; idx += 256) {
        int c = idx / 14, pp = idx - c * 14;
        tile[c * 15 + pp] = xp[(size_t)c * 196 + pp];
    }
    __syncthreads();

    const int warp = tid >> 5, lane = tid & 31;
    for (int pp = warp; pp < 14; pp += 8) {
        float s = 0.f, s2 = 0.f;
        for (int c = lane; c < 512; c += 32) {
            float v = tile[c * 15 + pp];
            s += v; s2 += v * v;
        }
        #pragma unroll
        for (int o = 16; o; o >>= 1) {
            s  += __shfl_xor_sync(0xffffffffu, s, o);
            s2 += __shfl_xor_sync(0xffffffffu, s2, o);
        }
        if (lane == 0) {
            float mu = s * (1.f / 512.f);
            float var = s2 * (1.f / 512.f) - mu * mu;
            smu[pp] = mu;
            srs[pp] = rsqrtf(var + 1e-5f);
        }
    }
    __syncthreads();

    for (int idx = tid; idx < 512 * 14; idx += 256) {
        int pp = idx >> 9, c = idx & 511;
        float raw = tile[c * 15 + pp];
        float v = (raw - smu[pp]) * srs[pp] * w[c] + bns[c];
        int hs = (h + 11) % 14, ws = (pp + 11) % 14;  // roll -SHIFT
        int m = bb * 196 + ((hs / 7) * 2 + ws / 7) * 49 + (hs % 7) * 7 + (ws % 7);
        g_XW[(size_t)m * 512 + c] = fp8(v);
        g_XT[(size_t)m * 512 + c] = raw;
    }
}

// ---- LN2: token-major g_X1 -> g_Z (e4m3) ----
__global__ __launch_bounds__(256)
void ln2_kernel(const float* __restrict__ w, const float* __restrict__ bns) {
    const int warp = threadIdx.x >> 5, lane = threadIdx.x & 31;
    const int m = blockIdx.x * 8 + warp;
    const float4* row = reinterpret_cast<const float4*>(g_X1 + (size_t)m * 512);
    float4 v[4];
    float s = 0.f, s2 = 0.f;
    #pragma unroll
    for (int j = 0; j < 4; ++j) {
        v[j] = row[lane + j * 32];
        s  += v[j].x + v[j].y + v[j].z + v[j].w;
        s2 += v[j].x * v[j].x + v[j].y * v[j].y + v[j].z * v[j].z + v[j].w * v[j].w;
    }
    #pragma unroll
    for (int o = 16; o; o >>= 1) {
        s  += __shfl_xor_sync(0xffffffffu, s, o);
        s2 += __shfl_xor_sync(0xffffffffu, s2, o);
    }
    const float mu = s * (1.f / 512.f);
    const float rs = rsqrtf(s2 * (1.f / 512.f) - mu * mu + 1e-5f);
    uint32_t* zrow = reinterpret_cast<uint32_t*>(g_Z + (size_t)m * 512);
    #pragma unroll
    for (int j = 0; j < 4; ++j) {
        const int c = (lane + j * 32) * 4;
        float o0 = (v[j].x - mu) * rs * w[c]     + bns[c];
        float o1 = (v[j].y - mu) * rs * w[c + 1] + bns[c + 1];
        float o2 = (v[j].z - mu) * rs * w[c + 2] + bns[c + 2];
        float o3 = (v[j].w - mu) * rs * w[c + 3] + bns[c + 3];
        zrow[lane + j * 32] = (uint32_t)pack8(o0, o1) | ((uint32_t)pack8(o2, o3) << 16);
    }
}

// ---- FP8 MMA GEMM, f16 accumulate (R13 config: best known).
// Block 128x128x128, 256 threads / 8 warps (2m x 4n), warp tile 64x32,
// 3-stage cp.async, 2 CTAs/SM, single sync per chunk.
static constexpr int LDSB = 144;                     // bytes per smem row
static constexpr int SA_T = 128 * LDSB;              // 18432
static constexpr int STG  = 2 * SA_T;                // 36864 per stage (A+B)
static constexpr int GSM  = 3 * STG;                 // 110592 B

template <int K, int N, int MODE>
__global__ __launch_bounds__(256, 2)
void gemm_kernel(const float* __restrict__ bias, const float* __restrict__ gamma) {
    const uint8_t* A;
    const uint8_t* Bw;
    if constexpr (MODE == 0)      { A = g_XW;  Bw = g_QKVW; }
    else if constexpr (MODE == 1) { A = g_ATT; Bw = g_PROJW; }
    else if constexpr (MODE == 2) { A = g_Z;   Bw = g_FC1W; }
    else                          { A = g_HB;  Bw = g_FC2W; }

    extern __shared__ __align__(16) uint8_t smem[];

    const int tid = threadIdx.x;
    const int lane = tid & 31, warp = tid >> 5;
    const int wm = warp & 1, wn = warp >> 1;          // 2m x 4n
    const int m0 = blockIdx.x * 128, n0 = blockIdx.y * 128;

    uint32_t acc[4][4][2];                            // f16x2 accumulators
    #pragma unroll
    for (int a = 0; a < 4; ++a)
        #pragma unroll
        for (int b = 0; b < 4; ++b) { acc[a][b][0] = 0u; acc[a][b][1] = 0u; }

    auto load_chunk = [&](int l) {
        uint8_t* stA = smem + (l % 3) * STG;
        uint8_t* stB = stA + SA_T;
        const int k0 = l * 128;
        #pragma unroll
        for (int i = 0; i < 4; ++i) {                  // A: 128 rows x 128 B
            int c = tid + i * 256;
            int row = c >> 3, cc = (c & 7) * 16;
            cp16(&stA[row * LDSB + cc], A + (size_t)(m0 + row) * K + k0 + cc);
        }
        #pragma unroll
        for (int i = 0; i < 4; ++i) {                  // B: 128 rows x 128 B
            int c = tid + i * 256;
            int row = c >> 3, cc = (c & 7) * 16;
            cp16(&stB[row * LDSB + cc], Bw + (size_t)(n0 + row) * K + k0 + cc);
        }
        asm volatile("cp.async.commit_group;\n");
    };

    const int KT = K / 128;
    load_chunk(0);
    if (KT > 1) load_chunk(1);

    #pragma unroll 1
    for (int c = 0; c < KT; ++c) {
        if (c + 1 < KT) asm volatile("cp.async.wait_group 1;\n");
        else            asm volatile("cp.async.wait_group 0;\n");
        __syncthreads();
        if (c + 2 < KT) load_chunk(c + 2);
        const uint8_t* stA = smem + (c % 3) * STG;
        const uint8_t* stB = stA + SA_T;
        #pragma unroll
        for (int ks = 0; ks < 4; ++ks) {               // 4 k-steps of k=32
            const int kcol = ks * 32 + (lane >> 4) * 16;   // byte offset
            uint32_t af[4][4], bf[4][2];
            #pragma unroll
            for (int tm = 0; tm < 4; ++tm)
                ldm4(af[tm], &stA[(wm * 64 + tm * 16 + (lane & 15)) * LDSB + kcol]);
            #pragma unroll
            for (int tb = 0; tb < 2; ++tb) {
                uint32_t r[4];
                ldm4(r, &stB[(wn * 32 + tb * 16 + (lane & 15)) * LDSB + kcol]);
                bf[2 * tb][0] = r[0]; bf[2 * tb][1] = r[2];
                bf[2 * tb + 1][0] = r[1]; bf[2 * tb + 1][1] = r[3];
            }
            #pragma unroll
            for (int tm = 0; tm < 4; ++tm)
                #pragma unroll
                for (int tn = 0; tn < 4; ++tn)
                    mma_fp8h(acc[tm][tn], af[tm], bf[tn]);
        }
    }

    // epilogue: row-major token-order; unpack f16x2 accumulators
    const int g = lane >> 2, qq = lane & 3;
    const bool isqk = (n0 < 1024);                     // MODE 0: q/k vs v region
    #pragma unroll
    for (int tm = 0; tm < 4; ++tm) {
        #pragma unroll
        for (int hh = 0; hh < 2; ++hh) {
            const int m = m0 + wm * 64 + tm * 16 + g + hh * 8;
            #pragma unroll
            for (int tn = 0; tn < 4; ++tn) {
                const int n = n0 + wn * 32 + tn * 8 + qq * 2;
                __half2 hv = *reinterpret_cast<const __half2*>(&acc[tm][tn][hh]);
                float v0 = __low2float(hv);
                float v1 = __high2float(hv);
                if constexpr (MODE == 0) {
                    v0 += g_QKVB[n]; v1 += g_QKVB[n + 1];
                    if (isqk) {
                        *reinterpret_cast<uint16_t*>(&g_QK[(size_t)m * 1024 + n]) = pack8(v0, v1);
                    } else {
                        *reinterpret_cast<__nv_bfloat162*>(&g_V[(size_t)m * 512 + (n - 1024)]) =
                            __floats2bfloat162_rn(v0, v1);
                    }
                } else if constexpr (MODE == 1) {
                    float2 xv = *reinterpret_cast<const float2*>(&g_XT[(size_t)m * 512 + n]);
                    float2 o;
                    o.x = xv.x + __ldg(&gamma[n])     * (v0 + __ldg(&bias[n]));
                    o.y = xv.y + __ldg(&gamma[n + 1]) * (v1 + __ldg(&bias[n + 1]));
                    *reinterpret_cast<float2*>(&g_X1[(size_t)m * 512 + n]) = o;
                } else if constexpr (MODE == 2) {
                    v0 += __ldg(&bias[n]); v1 += __ldg(&bias[n + 1]);
                    v0 *= normcdff(v0); v1 *= normcdff(v1);  // exact GELU
                    *reinterpret_cast<uint16_t*>(&g_HB[(size_t)m * 2048 + n]) = pack8(v0, v1);
                } else {
                    float2 xv = *reinterpret_cast<const float2*>(&g_X1[(size_t)m * 512 + n]);
                    float2 o;
                    o.x = xv.x + __ldg(&gamma[n])     * (v0 + __ldg(&bias[n]));
                    o.y = xv.y + __ldg(&gamma[n + 1]) * (v1 + __ldg(&bias[n + 1]));
                    *reinterpret_cast<float2*>(&g_X1[(size_t)m * 512 + n]) = o;  // in-place
                }
            }
        }
    }
}

// ---- final transpose: g_X1 token-major (window order) -> d_out NCHW fp32 ----
__global__ __launch_bounds__(256)
void tpose_kernel(float* __restrict__ out) {
    extern __shared__ float ts[];      // [196][129]
    __shared__ int ptab[196];
    const int b = blockIdx.x >> 2, cc = (blockIdx.x & 3) * 128;
    const int tid = threadIdx.x;
    if (tid < 196) {
        int wl = tid / 49, t = tid - wl * 49;
        int hs = (wl >> 1) * 7 + t / 7, ws = (wl & 1) * 7 + t % 7;
        ptab[tid] = ((hs + 3) % 14) * 14 + ((ws + 3) % 14);
    }
    __syncthreads();
    for (int i = tid; i < 196 * 128; i += 256) {
        int ml = i >> 7, c = i & 127;
        ts[ptab[ml] * 129 + c] = g_X1[((size_t)b * 196 + ml) * 512 + cc + c];
    }
    __syncthreads();
    for (int i = tid; i < 128 * 196; i += 256) {
        int c = i / 196, p = i - c * 196;
        out[(size_t)b * 100352 + (size_t)(cc + c) * 196 + p] = ts[p * 129 + c];
    }
}

// ---- attention: 2 (window,head) tasks / 128-thread block.
// S = Q K^T via ONE fp8 k32 mma step (Q,K e4m3); softmax fp32; P·V bf16.
__global__ __launch_bounds__(128) void attn_kernel() {
    __shared__ __align__(16) uint8_t       sQ8[2][64 * 48];
    __shared__ __align__(16) uint8_t       sK8[2][64 * 48];
    __shared__ __align__(16) __nv_bfloat16 sV [2][64 * 40];

    const int tid = threadIdx.x, lane = tid & 31, warp = tid >> 5;
    const int task0 = blockIdx.x * 2;

    for (int i = tid; i < 2 * 2 * 49 * 2; i += 128) {
        int tloc = i / 196, rem = i - tloc * 196;
        int tensor = rem / 98, rr = rem - tensor * 98;
        int row = rr >> 1, chunk = rr & 1;
        int task = task0 + tloc;
        int head = task & 15, wbi = task >> 4;
        int mbase = (wbi >> 2) * 196 + (wbi & 3) * 49;
        const uint4* src = reinterpret_cast<const uint4*>(
            &g_QK[(size_t)(mbase + row) * 1024 + tensor * 512 + head * 32 + chunk * 16]);
        uint8_t* dst = (tensor == 0 ? sQ8 : sK8)[tloc];
        *reinterpret_cast<uint4*>(&dst[row * 48 + chunk * 16]) = *src;
    }
    for (int i = tid; i < 2 * 49 * 4; i += 128) {
        int tloc = i / 196, rr = i - tloc * 196;
        int row = rr >> 2, chunk = rr & 3;
        int task = task0 + tloc;
        int head = task & 15, wbi = task >> 4;
        int mbase = (wbi >> 2) * 196 + (wbi & 3) * 49;
        const uint4* src = reinterpret_cast<const uint4*>(
            &g_V[(size_t)(mbase + row) * 512 + head * 32 + chunk * 8]);
        *reinterpret_cast<uint4*>(&sV[tloc][row * 40 + chunk * 8]) = *src;
    }
    for (int i = tid; i < 2 * 15 * 3; i += 128) {
        int tloc = i / 45, rr = i - tloc * 45;
        int row = 49 + rr / 3, chunk = rr % 3;
        *reinterpret_cast<uint4*>(&sQ8[tloc][row * 48 + chunk * 16]) = make_uint4(0, 0, 0, 0);
        *reinterpret_cast<uint4*>(&sK8[tloc][row * 48 + chunk * 16]) = make_uint4(0, 0, 0, 0);
    }
    for (int i = tid; i < 2 * 15 * 5; i += 128) {
        int tloc = i / 75, rr = i - tloc * 75;
        int row = 49 + rr / 5, chunk = rr % 5;
        *reinterpret_cast<uint4*>(&sV[tloc][row * 40 + chunk * 8]) = make_uint4(0, 0, 0, 0);
    }
    __syncthreads();

    const int tloc = warp >> 1, mhalf = warp & 1;
    const int task = task0 + tloc;
    const int head = task & 15, wbi = task >> 4;
    const int wl = wbi & 3;
    const int mbase = (wbi >> 2) * 196 + wl * 49;
    const int g = lane >> 2, qq = lane & 3;
    const uint8_t* Qs = sQ8[tloc];
    const uint8_t* Ks = sK8[tloc];
    const __nv_bfloat16* Vs = sV[tloc];

    float sacc[2][8][4];
    #pragma unroll
    for (int a = 0; a < 2; ++a)
        #pragma unroll
        for (int b = 0; b < 8; ++b)
            #pragma unroll
            for (int c = 0; c < 4; ++c) sacc[a][b][c] = 0.f;

    {
        const int kcol = (lane >> 4) * 16;
        uint32_t af[2][4], bf[8][2];
        #pragma unroll
        for (int tm = 0; tm < 2; ++tm)
            ldm4(af[tm], &Qs[(mhalf * 32 + tm * 16 + (lane & 15)) * 48 + kcol]);
        #pragma unroll
        for (int tb = 0; tb < 4; ++tb) {
            uint32_t r[4];
            ldm4(r, &Ks[(tb * 16 + (lane & 15)) * 48 + kcol]);
            bf[2 * tb][0] = r[0]; bf[2 * tb][1] = r[2];
            bf[2 * tb + 1][0] = r[1]; bf[2 * tb + 1][1] = r[3];
        }
        #pragma unroll
        for (int tm = 0; tm < 2; ++tm)
            #pragma unroll
            for (int nf = 0; nf < 8; ++nf)
                mma_fp8(sacc[tm][nf], af[tm], bf[nf]);
    }

    const __half* bt = g_BM + (wl * 16 + head) * 2450;
    float rsum[2][2];
    #pragma unroll
    for (int tm = 0; tm < 2; ++tm) {
        #pragma unroll
        for (int rr = 0; rr < 2; ++rr) {
            const int row = mhalf * 32 + tm * 16 + g + rr * 8;
            if (row < 49) {
                #pragma unroll
                for (int nf = 0; nf < 8; ++nf) {
                    const int col = nf * 8 + 2 * qq;
                    if (col < 49) {
                        float2 b2 = __half22float2(
                            *reinterpret_cast<const __half2*>(&bt[row * 50 + col]));
                        sacc[tm][nf][rr * 2 + 0] += b2.x;
                        sacc[tm][nf][rr * 2 + 1] =
                            (col + 1 < 49) ? sacc[tm][nf][rr * 2 + 1] + b2.y : -1e30f;
                    } else {
                        sacc[tm][nf][rr * 2 + 0] = -1e30f;
                        sacc[tm][nf][rr * 2 + 1] = -1e30f;
                    }
                }
            }
            float mx = -1e30f;
            #pragma unroll
            for (int nf = 0; nf < 8; ++nf)
                mx = fmaxf(mx, fmaxf(sacc[tm][nf][rr * 2], sacc[tm][nf][rr * 2 + 1]));
            mx = fmaxf(mx, __shfl_xor_sync(0xffffffffu, mx, 1));
            mx = fmaxf(mx, __shfl_xor_sync(0xffffffffu, mx, 2));
            float s = 0.f;
            #pragma unroll
            for (int nf = 0; nf < 8; ++nf) {
                #pragma unroll
                for (int j = 0; j < 2; ++j) {
                    float p = __expf(sacc[tm][nf][rr * 2 + j] - mx);
                    sacc[tm][nf][rr * 2 + j] = p;
                    s += p;
                }
            }
            s += __shfl_xor_sync(0xffffffffu, s, 1);
            s += __shfl_xor_sync(0xffffffffu, s, 2);
            rsum[tm][rr] = s;
        }
    }

    float dacc[2][4][4];
    #pragma unroll
    for (int a = 0; a < 2; ++a)
        #pragma unroll
        for (int b = 0; b < 4; ++b)
            #pragma unroll
            for (int c = 0; c < 4; ++c) dacc[a][b][c] = 0.f;

    #pragma unroll
    for (int kk = 0; kk < 4; ++kk) {
        uint32_t pa[2][4];
        #pragma unroll
        for (int tm = 0; tm < 2; ++tm) {
            pa[tm][0] = packbf(sacc[tm][2 * kk][0],     sacc[tm][2 * kk][1]);
            pa[tm][1] = packbf(sacc[tm][2 * kk][2],     sacc[tm][2 * kk][3]);
            pa[tm][2] = packbf(sacc[tm][2 * kk + 1][0], sacc[tm][2 * kk + 1][1]);
            pa[tm][3] = packbf(sacc[tm][2 * kk + 1][2], sacc[tm][2 * kk + 1][3]);
        }
        uint32_t bv[4][2];
        #pragma unroll
        for (int half = 0; half < 2; ++half) {
            uint32_t r[4];
            ldm4t(r, &Vs[(kk * 16 + (lane & 15)) * 40 + half * 16 + (lane >> 4) * 8]);
            bv[half * 2 + 0][0] = r[0]; bv[half * 2 + 0][1] = r[1];
            bv[half * 2 + 1][0] = r[2]; bv[half * 2 + 1][1] = r[3];
        }
        #pragma unroll
        for (int tm = 0; tm < 2; ++tm)
            #pragma unroll
            for (int tn = 0; tn < 4; ++tn)
                mma_bf16(dacc[tm][tn], pa[tm], bv[tn]);
    }

    #pragma unroll
    for (int tm = 0; tm < 2; ++tm) {
        #pragma unroll
        for (int rr = 0; rr < 2; ++rr) {
            const int row = mhalf * 32 + tm * 16 + g + rr * 8;
            if (row < 49) {
                const float inv = 1.f / rsum[tm][rr];
                #pragma unroll
                for (int tn = 0; tn < 4; ++tn) {
                    const int col = tn * 8 + 2 * qq;
                    *reinterpret_cast<uint16_t*>(
                        &g_ATT[(size_t)(mbase + row) * 512 + head * 32 + col]) =
                        pack8(dacc[tm][tn][rr * 2] * inv, dacc[tm][tn][rr * 2 + 1] * inv);
                }
            }
        }
    }
}

extern "C" void kernel_launch(void* const* d_in, const int* in_sizes, int n_in,
                              void* d_out, int out_size) {
    const float* x      = (const float*)d_in[0];
    const float* ln1_w  = (const float*)d_in[1];
    const float* ln1_b  = (const float*)d_in[2];
    const float* qkv_w  = (const float*)d_in[3];
    const float* qkv_b  = (const float*)d_in[4];
    const float* relb   = (const float*)d_in[5];
    const float* proj_w = (const float*)d_in[6];
    const float* proj_b = (const float*)d_in[7];
    const float* gamma1 = (const float*)d_in[8];
    const float* ln2_w  = (const float*)d_in[9];
    const float* ln2_b  = (const float*)d_in[10];
    const float* fc1_w  = (const float*)d_in[11];
    const float* fc1_b  = (const float*)d_in[12];
    const float* fc2_w  = (const float*)d_in[13];
    const float* fc2_b  = (const float*)d_in[14];
    const float* gamma2 = (const float*)d_in[15];
    float* out = (float*)d_out;

    const int TSM = 196 * 129 * 4;
    cudaFuncSetAttribute(gemm_kernel<512, 1536, 0>, cudaFuncAttributeMaxDynamicSharedMemorySize, GSM);
    cudaFuncSetAttribute(gemm_kernel<512, 512, 1>,  cudaFuncAttributeMaxDynamicSharedMemorySize, GSM);
    cudaFuncSetAttribute(gemm_kernel<512, 2048, 2>, cudaFuncAttributeMaxDynamicSharedMemorySize, GSM);
    cudaFuncSetAttribute(gemm_kernel<2048, 512, 3>, cudaFuncAttributeMaxDynamicSharedMemorySize, GSM);
    cudaFuncSetAttribute(tpose_kernel, cudaFuncAttributeMaxDynamicSharedMemorySize, TSM);

    const int PREP = W4 + 64 * 2450 + 1536;
    prep_kernel<<<(PREP + 255) / 256, 256>>>(qkv_w, proj_w, fc1_w, fc2_w, relb, qkv_b);
    ln1_kernel<<<128 * 14, 256>>>(x, ln1_w, ln1_b);
    gemm_kernel<512, 1536, 0><<<dim3(196, 12), 256, GSM>>>(nullptr, nullptr);
    attn_kernel<<<4096, 128>>>();
    gemm_kernel<512, 512, 1><<<dim3(196, 4), 256, GSM>>>(proj_b, gamma1);
    ln2_kernel<<<3136, 256>>>(ln2_w, ln2_b);
    gemm_kernel<512, 2048, 2><<<dim3(196, 16), 256, GSM>>>(fc1_b, nullptr);
    gemm_kernel<2048, 512, 3><<<dim3(196, 4), 256, GSM>>>(fc2_b, gamma2);
    tpose_kernel<<<512, 256, TSM>>>(out);
}

// round 16
// speedup vs baseline: 1.4759x; 1.4759x over previous
#include <cuda_runtime.h>
#include <cuda_bf16.h>
#include <cuda_fp16.h>
#include <cstdint>

// B=128, C=512, H=W=14, WIN=7, SHIFT=3, HEADS=16, HD=32, HID=2048
static constexpr int MT = 25088;  // B*H*W = B*nW*N

// ---- scratch (__device__ globals: allocation-free kernel_launch) ----
__device__ __align__(16) uint8_t       g_XW [(size_t)MT * 512];   // LN1 tokens, e4m3
__device__ __align__(16) float         g_XT [(size_t)MT * 512];   // x fp32 token-major
__device__ __align__(16) uint8_t       g_QK [(size_t)MT * 1024];  // q(0..511), k(512..1023) e4m3
__device__ __align__(16) __nv_bfloat16 g_V  [(size_t)MT * 512];   // v bf16
__device__ __align__(16) uint8_t       g_ATT[(size_t)MT * 512];   // e4m3
__device__ __align__(16) float         g_X1 [(size_t)MT * 512];   // running residual fp32
__device__ __align__(16) uint8_t       g_Z  [(size_t)MT * 512];   // e4m3
__device__ __align__(16) uint8_t       g_HB [(size_t)MT * 2048];  // e4m3
__device__ __align__(16) uint8_t g_QKVW[1536 * 512];
__device__ __align__(16) uint8_t g_PROJW[512 * 512];
__device__ __align__(16) uint8_t g_FC1W[2048 * 512];
__device__ __align__(16) uint8_t g_FC2W[512 * 2048];
__device__ float g_QKVB[1536];
__device__ float g_BM[64 * 49 * 50];    // [wl][head] combined bias+mask, stride-50 rows

// ---- PTX helpers ----
__device__ __forceinline__ void cp16(void* sm, const void* gm) {
    uint32_t s = (uint32_t)__cvta_generic_to_shared(sm);
    asm volatile("cp.async.cg.shared.global [%0], [%1], 16;\n" :: "r"(s), "l"(gm));
}
__device__ __forceinline__ void ldm4(uint32_t r[4], const void* p) {
    uint32_t a = (uint32_t)__cvta_generic_to_shared(p);
    asm volatile("ldmatrix.sync.aligned.m8n8.x4.shared.b16 {%0,%1,%2,%3}, [%4];\n"
                 : "=r"(r[0]), "=r"(r[1]), "=r"(r[2]), "=r"(r[3]) : "r"(a));
}
__device__ __forceinline__ void ldm4t(uint32_t r[4], const void* p) {
    uint32_t a = (uint32_t)__cvta_generic_to_shared(p);
    asm volatile("ldmatrix.sync.aligned.m8n8.x4.trans.shared.b16 {%0,%1,%2,%3}, [%4];\n"
                 : "=r"(r[0]), "=r"(r[1]), "=r"(r[2]), "=r"(r[3]) : "r"(a));
}
__device__ __forceinline__ void mma_bf16(float c[4], const uint32_t a[4], const uint32_t b[2]) {
    asm volatile("mma.sync.aligned.m16n8k16.row.col.f32.bf16.bf16.f32 "
                 "{%0,%1,%2,%3}, {%4,%5,%6,%7}, {%8,%9}, {%0,%1,%2,%3};\n"
                 : "+f"(c[0]), "+f"(c[1]), "+f"(c[2]), "+f"(c[3])
                 : "r"(a[0]), "r"(a[1]), "r"(a[2]), "r"(a[3]), "r"(b[0]), "r"(b[1]));
}
__device__ __forceinline__ void mma_fp8(float c[4], const uint32_t a[4], const uint32_t b[2]) {
    asm volatile("mma.sync.aligned.m16n8k32.row.col.f32.e4m3.e4m3.f32 "
                 "{%0,%1,%2,%3}, {%4,%5,%6,%7}, {%8,%9}, {%0,%1,%2,%3};\n"
                 : "+f"(c[0]), "+f"(c[1]), "+f"(c[2]), "+f"(c[3])
                 : "r"(a[0]), "r"(a[1]), "r"(a[2]), "r"(a[3]), "r"(b[0]), "r"(b[1]));
}
// f16-accumulate fp8 mma (halves accumulator registers)
__device__ __forceinline__ void mma_fp8h(uint32_t c[2], const uint32_t a[4], const uint32_t b[2]) {
    asm volatile("mma.sync.aligned.m16n8k32.row.col.f16.e4m3.e4m3.f16 "
                 "{%0,%1}, {%2,%3,%4,%5}, {%6,%7}, {%0,%1};\n"
                 : "+r"(c[0]), "+r"(c[1])
                 : "r"(a[0]), "r"(a[1]), "r"(a[2]), "r"(a[3]), "r"(b[0]), "r"(b[1]));
}
__device__ __forceinline__ uint32_t packbf(float a, float b) {
    __nv_bfloat162 t = __floats2bfloat162_rn(a, b);
    return *reinterpret_cast<uint32_t*>(&t);
}
__device__ __forceinline__ uint16_t pack8(float lo, float hi) {
    uint16_t r;
    asm("cvt.rn.satfinite.e4m3x2.f32 %0, %1, %2;" : "=h"(r) : "f"(hi), "f"(lo));
    return r;
}
__device__ __forceinline__ uint8_t fp8(float v) {
    return (uint8_t)(pack8(v, 0.f) & 0xFF);
}

// ---- prep: weights -> e4m3 vectorized, bias/mask tables, qkv bias ----
static constexpr int EW_ELEM = 512 * 6144;
static constexpr int W4 = EW_ELEM / 4;
__global__ void prep_kernel(const float* __restrict__ qkvw, const float* __restrict__ projw,
                            const float* __restrict__ fc1w, const float* __restrict__ fc2w,
                            const float* __restrict__ rel_bias, const float* __restrict__ qkvb) {
    int t = blockIdx.x * 256 + threadIdx.x;
    const int E0 = 1536 * 512, E1 = 512 * 512, E2 = 2048 * 512;
    if (t < W4) {
        int i = t * 4;
        float4 v;
        uint8_t* dst;
        if (i < E0) {
            v = *reinterpret_cast<const float4*>(qkvw + i);
            if (i < 512 * 512) {
                v.x *= 0.17677669529663687f; v.y *= 0.17677669529663687f;
                v.z *= 0.17677669529663687f; v.w *= 0.17677669529663687f;
            }
            dst = g_QKVW + i;
        } else if (i < E0 + E1) {
            v = *reinterpret_cast<const float4*>(projw + (i - E0));
            dst = g_PROJW + (i - E0);
        } else if (i < E0 + E1 + E2) {
            v = *reinterpret_cast<const float4*>(fc1w + (i - E0 - E1));
            dst = g_FC1W + (i - E0 - E1);
        } else {
            v = *reinterpret_cast<const float4*>(fc2w + (i - E0 - E1 - E2));
            dst = g_FC2W + (i - E0 - E1 - E2);
        }
        *reinterpret_cast<uint32_t*>(dst) =
            (uint32_t)pack8(v.x, v.y) | ((uint32_t)pack8(v.z, v.w) << 16);
    } else if (t < W4 + 64 * 2450) {
        int j = t - W4;
        int combo = j / 2450, e = j - combo * 2450;
        int wl = combo >> 4, head = combo & 15;
        int a = e / 50, b = e - a * 50;
        float v = 0.f;
        if (b < 49) {
            int ra = a / 7, ca = a - ra * 7, rb = b / 7, cb = b - rb * 7;
            v = rel_bias[((ra - rb + 6) * 13 + (ca - cb + 6)) * 16 + head];
            int wh = wl >> 1, ww = wl & 1;
            int ha = wh * 7 + ra, wa = ww * 7 + ca;
            int hb = wh * 7 + rb, wb = ww * 7 + cb;
            int ga = (ha < 7 ? 0 : (ha < 11 ? 1 : 2)) * 3 + (wa < 7 ? 0 : (wa < 11 ? 1 : 2));
            int gb = (hb < 7 ? 0 : (hb < 11 ? 1 : 2)) * 3 + (wb < 7 ? 0 : (wb < 11 ? 1 : 2));
            if (ga != gb) v -= 100.f;
        }
        g_BM[j] = v;
    } else if (t < W4 + 64 * 2450 + 1536) {
        int j = t - W4 - 64 * 2450;
        g_QKVB[j] = qkvb[j] * (j < 512 ? 0.17677669529663687f : 1.f);
    }
}

// ---- LN1: x(NCHW) -> g_XW e4m3 tokens (roll + window partition) AND g_XT fp32 copy ----
__global__ __launch_bounds__(256)
void ln1_kernel(const float* __restrict__ xin, const float* __restrict__ w,
                const float* __restrict__ bns) {
    __shared__ float tile[512 * 15];
    __shared__ float smu[14], srs[14];
    const int bb = blockIdx.x / 14, h = blockIdx.x - bb * 14;
    const float* xp = xin + (size_t)bb * 100352 + h * 14;
    const int tid = threadIdx.x;

    for (int idx = tid; idx < 512 * 14; idx += 256) {
        int c = idx / 14, pp = idx - c * 14;
        tile[c * 15 + pp] = xp[(size_t)c * 196 + pp];
    }
    __syncthreads();

    const int warp = tid >> 5, lane = tid & 31;
    for (int pp = warp; pp < 14; pp += 8) {
        float s = 0.f, s2 = 0.f;
        for (int c = lane; c < 512; c += 32) {
            float v = tile[c * 15 + pp];
            s += v; s2 += v * v;
        }
        #pragma unroll
        for (int o = 16; o; o >>= 1) {
            s  += __shfl_xor_sync(0xffffffffu, s, o);
            s2 += __shfl_xor_sync(0xffffffffu, s2, o);
        }
        if (lane == 0) {
            float mu = s * (1.f / 512.f);
            float var = s2 * (1.f / 512.f) - mu * mu;
            smu[pp] = mu;
            srs[pp] = rsqrtf(var + 1e-5f);
        }
    }
    __syncthreads();

    for (int idx = tid; idx < 512 * 14; idx += 256) {
        int pp = idx >> 9, c = idx & 511;
        float raw = tile[c * 15 + pp];
        float v = (raw - smu[pp]) * srs[pp] * w[c] + bns[c];
        int hs = (h + 11) % 14, ws = (pp + 11) % 14;  // roll -SHIFT
        int m = bb * 196 + ((hs / 7) * 2 + ws / 7) * 49 + (hs % 7) * 7 + (ws % 7);
        g_XW[(size_t)m * 512 + c] = fp8(v);
        g_XT[(size_t)m * 512 + c] = raw;
    }
}

// ---- LN2: token-major g_X1 -> g_Z (e4m3) ----
__global__ __launch_bounds__(256)
void ln2_kernel(const float* __restrict__ w, const float* __restrict__ bns) {
    const int warp = threadIdx.x >> 5, lane = threadIdx.x & 31;
    const int m = blockIdx.x * 8 + warp;
    const float4* row = reinterpret_cast<const float4*>(g_X1 + (size_t)m * 512);
    float4 v[4];
    float s = 0.f, s2 = 0.f;
    #pragma unroll
    for (int j = 0; j < 4; ++j) {
        v[j] = row[lane + j * 32];
        s  += v[j].x + v[j].y + v[j].z + v[j].w;
        s2 += v[j].x * v[j].x + v[j].y * v[j].y + v[j].z * v[j].z + v[j].w * v[j].w;
    }
    #pragma unroll
    for (int o = 16; o; o >>= 1) {
        s  += __shfl_xor_sync(0xffffffffu, s, o);
        s2 += __shfl_xor_sync(0xffffffffu, s2, o);
    }
    const float mu = s * (1.f / 512.f);
    const float rs = rsqrtf(s2 * (1.f / 512.f) - mu * mu + 1e-5f);
    uint32_t* zrow = reinterpret_cast<uint32_t*>(g_Z + (size_t)m * 512);
    #pragma unroll
    for (int j = 0; j < 4; ++j) {
        const int c = (lane + j * 32) * 4;
        float o0 = (v[j].x - mu) * rs * w[c]     + bns[c];
        float o1 = (v[j].y - mu) * rs * w[c + 1] + bns[c + 1];
        float o2 = (v[j].z - mu) * rs * w[c + 2] + bns[c + 2];
        float o3 = (v[j].w - mu) * rs * w[c + 3] + bns[c + 3];
        zrow[lane + j * 32] = (uint32_t)pack8(o0, o1) | ((uint32_t)pack8(o2, o3) << 16);
    }
}

// ---- FP8 MMA GEMM, f16 accumulate (best known config).
// Block 128x128x128, 256 threads / 8 warps (2m x 4n), warp tile 64x32,
// 3-stage cp.async, 2 CTAs/SM, single sync per chunk.
static constexpr int LDSB = 144;                     // bytes per smem row
static constexpr int SA_T = 128 * LDSB;              // 18432
static constexpr int STG  = 2 * SA_T;                // 36864 per stage (A+B)
static constexpr int GSM  = 3 * STG;                 // 110592 B

template <int K, int N, int MODE>
__global__ __launch_bounds__(256, 2)
void gemm_kernel(const float* __restrict__ bias, const float* __restrict__ gamma) {
    const uint8_t* A;
    const uint8_t* Bw;
    if constexpr (MODE == 0)      { A = g_XW;  Bw = g_QKVW; }
    else if constexpr (MODE == 1) { A = g_ATT; Bw = g_PROJW; }
    else if constexpr (MODE == 2) { A = g_Z;   Bw = g_FC1W; }
    else                          { A = g_HB;  Bw = g_FC2W; }

    extern __shared__ __align__(16) uint8_t smem[];

    const int tid = threadIdx.x;
    const int lane = tid & 31, warp = tid >> 5;
    const int wm = warp & 1, wn = warp >> 1;          // 2m x 4n
    const int m0 = blockIdx.x * 128, n0 = blockIdx.y * 128;

    uint32_t acc[4][4][2];                            // f16x2 accumulators
    #pragma unroll
    for (int a = 0; a < 4; ++a)
        #pragma unroll
        for (int b = 0; b < 4; ++b) { acc[a][b][0] = 0u; acc[a][b][1] = 0u; }

    auto load_chunk = [&](int l) {
        uint8_t* stA = smem + (l % 3) * STG;
        uint8_t* stB = stA + SA_T;
        const int k0 = l * 128;
        #pragma unroll
        for (int i = 0; i < 4; ++i) {                  // A: 128 rows x 128 B
            int c = tid + i * 256;
            int row = c >> 3, cc = (c & 7) * 16;
            cp16(&stA[row * LDSB + cc], A + (size_t)(m0 + row) * K + k0 + cc);
        }
        #pragma unroll
        for (int i = 0; i < 4; ++i) {                  // B: 128 rows x 128 B
            int c = tid + i * 256;
            int row = c >> 3, cc = (c & 7) * 16;
            cp16(&stB[row * LDSB + cc], Bw + (size_t)(n0 + row) * K + k0 + cc);
        }
        asm volatile("cp.async.commit_group;\n");
    };

    const int KT = K / 128;
    load_chunk(0);
    if (KT > 1) load_chunk(1);

    #pragma unroll 1
    for (int c = 0; c < KT; ++c) {
        if (c + 1 < KT) asm volatile("cp.async.wait_group 1;\n");
        else            asm volatile("cp.async.wait_group 0;\n");
        __syncthreads();
        if (c + 2 < KT) load_chunk(c + 2);
        const uint8_t* stA = smem + (c % 3) * STG;
        const uint8_t* stB = stA + SA_T;
        #pragma unroll
        for (int ks = 0; ks < 4; ++ks) {               // 4 k-steps of k=32
            const int kcol = ks * 32 + (lane >> 4) * 16;   // byte offset
            uint32_t af[4][4], bf[4][2];
            #pragma unroll
            for (int tm = 0; tm < 4; ++tm)
                ldm4(af[tm], &stA[(wm * 64 + tm * 16 + (lane & 15)) * LDSB + kcol]);
            #pragma unroll
            for (int tb = 0; tb < 2; ++tb) {
                uint32_t r[4];
                ldm4(r, &stB[(wn * 32 + tb * 16 + (lane & 15)) * LDSB + kcol]);
                bf[2 * tb][0] = r[0]; bf[2 * tb][1] = r[2];
                bf[2 * tb + 1][0] = r[1]; bf[2 * tb + 1][1] = r[3];
            }
            #pragma unroll
            for (int tm = 0; tm < 4; ++tm)
                #pragma unroll
                for (int tn = 0; tn < 4; ++tn)
                    mma_fp8h(acc[tm][tn], af[tm], bf[tn]);
        }
    }

    // epilogue: row-major token-order; unpack f16x2 accumulators
    const int g = lane >> 2, qq = lane & 3;
    const bool isqk = (n0 < 1024);                     // MODE 0: q/k vs v region
    #pragma unroll
    for (int tm = 0; tm < 4; ++tm) {
        #pragma unroll
        for (int hh = 0; hh < 2; ++hh) {
            const int m = m0 + wm * 64 + tm * 16 + g + hh * 8;
            #pragma unroll
            for (int tn = 0; tn < 4; ++tn) {
                const int n = n0 + wn * 32 + tn * 8 + qq * 2;
                __half2 hv = *reinterpret_cast<const __half2*>(&acc[tm][tn][hh]);
                float v0 = __low2float(hv);
                float v1 = __high2float(hv);
                if constexpr (MODE == 0) {
                    v0 += g_QKVB[n]; v1 += g_QKVB[n + 1];
                    if (isqk) {
                        *reinterpret_cast<uint16_t*>(&g_QK[(size_t)m * 1024 + n]) = pack8(v0, v1);
                    } else {
                        *reinterpret_cast<__nv_bfloat162*>(&g_V[(size_t)m * 512 + (n - 1024)]) =
                            __floats2bfloat162_rn(v0, v1);
                    }
                } else if constexpr (MODE == 1) {
                    float2 xv = *reinterpret_cast<const float2*>(&g_XT[(size_t)m * 512 + n]);
                    float2 o;
                    o.x = xv.x + __ldg(&gamma[n])     * (v0 + __ldg(&bias[n]));
                    o.y = xv.y + __ldg(&gamma[n + 1]) * (v1 + __ldg(&bias[n + 1]));
                    *reinterpret_cast<float2*>(&g_X1[(size_t)m * 512 + n]) = o;
                } else if constexpr (MODE == 2) {
                    v0 += __ldg(&bias[n]); v1 += __ldg(&bias[n + 1]);
                    v0 *= normcdff(v0); v1 *= normcdff(v1);  // exact GELU
                    *reinterpret_cast<uint16_t*>(&g_HB[(size_t)m * 2048 + n]) = pack8(v0, v1);
                } else {
                    float2 xv = *reinterpret_cast<const float2*>(&g_X1[(size_t)m * 512 + n]);
                    float2 o;
                    o.x = xv.x + __ldg(&gamma[n])     * (v0 + __ldg(&bias[n]));
                    o.y = xv.y + __ldg(&gamma[n + 1]) * (v1 + __ldg(&bias[n + 1]));
                    *reinterpret_cast<float2*>(&g_X1[(size_t)m * 512 + n]) = o;  // in-place
                }
            }
        }
    }
}

// ---- final transpose: g_X1 token-major (window order) -> d_out NCHW fp32 ----
__global__ __launch_bounds__(256)
void tpose_kernel(float* __restrict__ out) {
    extern __shared__ float ts[];      // [196][129]
    __shared__ int ptab[196];
    const int b = blockIdx.x >> 2, cc = (blockIdx.x & 3) * 128;
    const int tid = threadIdx.x;
    if (tid < 196) {
        int wl = tid / 49, t = tid - wl * 49;
        int hs = (wl >> 1) * 7 + t / 7, ws = (wl & 1) * 7 + t % 7;
        ptab[tid] = ((hs + 3) % 14) * 14 + ((ws + 3) % 14);
    }
    __syncthreads();
    for (int i = tid; i < 196 * 128; i += 256) {
        int ml = i >> 7, c = i & 127;
        ts[ptab[ml] * 129 + c] = g_X1[((size_t)b * 196 + ml) * 512 + cc + c];
    }
    __syncthreads();
    for (int i = tid; i < 128 * 196; i += 256) {
        int c = i / 196, p = i - c * 196;
        out[(size_t)b * 100352 + (size_t)(cc + c) * 196 + p] = ts[p * 129 + c];
    }
}

// ---- attention: 2 (window,head) tasks / 128-thread block.
// S = Q K^T via ONE fp8 k32 mma step (Q,K e4m3); softmax fp32; P·V bf16.
__global__ __launch_bounds__(128) void attn_kernel() {
    __shared__ __align__(16) uint8_t       sQ8[2][64 * 48];
    __shared__ __align__(16) uint8_t       sK8[2][64 * 48];
    __shared__ __align__(16) __nv_bfloat16 sV [2][64 * 40];

    const int tid = threadIdx.x, lane = tid & 31, warp = tid >> 5;
    const int task0 = blockIdx.x * 2;

    for (int i = tid; i < 2 * 2 * 49 * 2; i += 128) {
        int tloc = i / 196, rem = i - tloc * 196;
        int tensor = rem / 98, rr = rem - tensor * 98;
        int row = rr >> 1, chunk = rr & 1;
        int task = task0 + tloc;
        int head = task & 15, wbi = task >> 4;
        int mbase = (wbi >> 2) * 196 + (wbi & 3) * 49;
        const uint4* src = reinterpret_cast<const uint4*>(
            &g_QK[(size_t)(mbase + row) * 1024 + tensor * 512 + head * 32 + chunk * 16]);
        uint8_t* dst = (tensor == 0 ? sQ8 : sK8)[tloc];
        *reinterpret_cast<uint4*>(&dst[row * 48 + chunk * 16]) = *src;
    }
    for (int i = tid; i < 2 * 49 * 4; i += 128) {
        int tloc = i / 196, rr = i - tloc * 196;
        int row = rr >> 2, chunk = rr & 3;
        int task = task0 + tloc;
        int head = task & 15, wbi = task >> 4;
        int mbase = (wbi >> 2) * 196 + (wbi & 3) * 49;
        const uint4* src = reinterpret_cast<const uint4*>(
            &g_V[(size_t)(mbase + row) * 512 + head * 32 + chunk * 8]);
        *reinterpret_cast<uint4*>(&sV[tloc][row * 40 + chunk * 8]) = *src;
    }
    for (int i = tid; i < 2 * 15 * 3; i += 128) {
        int tloc = i / 45, rr = i - tloc * 45;
        int row = 49 + rr / 3, chunk = rr % 3;
        *reinterpret_cast<uint4*>(&sQ8[tloc][row * 48 + chunk * 16]) = make_uint4(0, 0, 0, 0);
        *reinterpret_cast<uint4*>(&sK8[tloc][row * 48 + chunk * 16]) = make_uint4(0, 0, 0, 0);
    }
    for (int i = tid; i < 2 * 15 * 5; i += 128) {
        int tloc = i / 75, rr = i - tloc * 75;
        int row = 49 + rr / 5, chunk = rr % 5;
        *reinterpret_cast<uint4*>(&sV[tloc][row * 40 + chunk * 8]) = make_uint4(0, 0, 0, 0);
    }
    __syncthreads();

    const int tloc = warp >> 1, mhalf = warp & 1;
    const int task = task0 + tloc;
    const int head = task & 15, wbi = task >> 4;
    const int wl = wbi & 3;
    const int mbase = (wbi >> 2) * 196 + wl * 49;
    const int g = lane >> 2, qq = lane & 3;
    const uint8_t* Qs = sQ8[tloc];
    const uint8_t* Ks = sK8[tloc];
    const __nv_bfloat16* Vs = sV[tloc];

    float sacc[2][8][4];
    #pragma unroll
    for (int a = 0; a < 2; ++a)
        #pragma unroll
        for (int b = 0; b < 8; ++b)
            #pragma unroll
            for (int c = 0; c < 4; ++c) sacc[a][b][c] = 0.f;

    {
        const int kcol = (lane >> 4) * 16;
        uint32_t af[2][4], bf[8][2];
        #pragma unroll
        for (int tm = 0; tm < 2; ++tm)
            ldm4(af[tm], &Qs[(mhalf * 32 + tm * 16 + (lane & 15)) * 48 + kcol]);
        #pragma unroll
        for (int tb = 0; tb < 4; ++tb) {
            uint32_t r[4];
            ldm4(r, &Ks[(tb * 16 + (lane & 15)) * 48 + kcol]);
            bf[2 * tb][0] = r[0]; bf[2 * tb][1] = r[2];
            bf[2 * tb + 1][0] = r[1]; bf[2 * tb + 1][1] = r[3];
        }
        #pragma unroll
        for (int tm = 0; tm < 2; ++tm)
            #pragma unroll
            for (int nf = 0; nf < 8; ++nf)
                mma_fp8(sacc[tm][nf], af[tm], bf[nf]);
    }

    const float* bt = g_BM + (wl * 16 + head) * 2450;
    float rsum[2][2];
    #pragma unroll
    for (int tm = 0; tm < 2; ++tm) {
        #pragma unroll
        for (int rr = 0; rr < 2; ++rr) {
            const int row = mhalf * 32 + tm * 16 + g + rr * 8;
            if (row < 49) {
                #pragma unroll
                for (int nf = 0; nf < 8; ++nf) {
                    const int col = nf * 8 + 2 * qq;
                    if (col < 49) {
                        float2 b2 = *reinterpret_cast<const float2*>(&bt[row * 50 + col]);
                        sacc[tm][nf][rr * 2 + 0] += b2.x;
                        sacc[tm][nf][rr * 2 + 1] =
                            (col + 1 < 49) ? sacc[tm][nf][rr * 2 + 1] + b2.y : -1e30f;
                    } else {
                        sacc[tm][nf][rr * 2 + 0] = -1e30f;
                        sacc[tm][nf][rr * 2 + 1] = -1e30f;
                    }
                }
            }
            float mx = -1e30f;
            #pragma unroll
            for (int nf = 0; nf < 8; ++nf)
                mx = fmaxf(mx, fmaxf(sacc[tm][nf][rr * 2], sacc[tm][nf][rr * 2 + 1]));
            mx = fmaxf(mx, __shfl_xor_sync(0xffffffffu, mx, 1));
            mx = fmaxf(mx, __shfl_xor_sync(0xffffffffu, mx, 2));
            float s = 0.f;
            #pragma unroll
            for (int nf = 0; nf < 8; ++nf) {
                #pragma unroll
                for (int j = 0; j < 2; ++j) {
                    float p = __expf(sacc[tm][nf][rr * 2 + j] - mx);
                    sacc[tm][nf][rr * 2 + j] = p;
                    s += p;
                }
            }
            s += __shfl_xor_sync(0xffffffffu, s, 1);
            s += __shfl_xor_sync(0xffffffffu, s, 2);
            rsum[tm][rr] = s;
        }
    }

    float dacc[2][4][4];
    #pragma unroll
    for (int a = 0; a < 2; ++a)
        #pragma unroll
        for (int b = 0; b < 4; ++b)
            #pragma unroll
            for (int c = 0; c < 4; ++c) dacc[a][b][c] = 0.f;

    #pragma unroll
    for (int kk = 0; kk < 4; ++kk) {
        uint32_t pa[2][4];
        #pragma unroll
        for (int tm = 0; tm < 2; ++tm) {
            pa[tm][0] = packbf(sacc[tm][2 * kk][0],     sacc[tm][2 * kk][1]);
            pa[tm][1] = packbf(sacc[tm][2 * kk][2],     sacc[tm][2 * kk][3]);
            pa[tm][2] = packbf(sacc[tm][2 * kk + 1][0], sacc[tm][2 * kk + 1][1]);
            pa[tm][3] = packbf(sacc[tm][2 * kk + 1][2], sacc[tm][2 * kk + 1][3]);
        }
        uint32_t bv[4][2];
        #pragma unroll
        for (int half = 0; half < 2; ++half) {
            uint32_t r[4];
            ldm4t(r, &Vs[(kk * 16 + (lane & 15)) * 40 + half * 16 + (lane >> 4) * 8]);
            bv[half * 2 + 0][0] = r[0]; bv[half * 2 + 0][1] = r[1];
            bv[half * 2 + 1][0] = r[2]; bv[half * 2 + 1][1] = r[3];
        }
        #pragma unroll
        for (int tm = 0; tm < 2; ++tm)
            #pragma unroll
            for (int tn = 0; tn < 4; ++tn)
                mma_bf16(dacc[tm][tn], pa[tm], bv[tn]);
    }

    #pragma unroll
    for (int tm = 0; tm < 2; ++tm) {
        #pragma unroll
        for (int rr = 0; rr < 2; ++rr) {
            const int row = mhalf * 32 + tm * 16 + g + rr * 8;
            if (row < 49) {
                const float inv = 1.f / rsum[tm][rr];
                #pragma unroll
                for (int tn = 0; tn < 4; ++tn) {
                    const int col = tn * 8 + 2 * qq;
                    *reinterpret_cast<uint16_t*>(
                        &g_ATT[(size_t)(mbase + row) * 512 + head * 32 + col]) =
                        pack8(dacc[tm][tn][rr * 2] * inv, dacc[tm][tn][rr * 2 + 1] * inv);
                }
            }
        }
    }
}

extern "C" void kernel_launch(void* const* d_in, const int* in_sizes, int n_in,
                              void* d_out, int out_size) {
    const float* x      = (const float*)d_in[0];
    const float* ln1_w  = (const float*)d_in[1];
    const float* ln1_b  = (const float*)d_in[2];
    const float* qkv_w  = (const float*)d_in[3];
    const float* qkv_b  = (const float*)d_in[4];
    const float* relb   = (const float*)d_in[5];
    const float* proj_w = (const float*)d_in[6];
    const float* proj_b = (const float*)d_in[7];
    const float* gamma1 = (const float*)d_in[8];
    const float* ln2_w  = (const float*)d_in[9];
    const float* ln2_b  = (const float*)d_in[10];
    const float* fc1_w  = (const float*)d_in[11];
    const float* fc1_b  = (const float*)d_in[12];
    const float* fc2_w  = (const float*)d_in[13];
    const float* fc2_b  = (const float*)d_in[14];
    const float* gamma2 = (const float*)d_in[15];
    float* out = (float*)d_out;

    const int TSM = 196 * 129 * 4;
    cudaFuncSetAttribute(gemm_kernel<512, 1536, 0>, cudaFuncAttributeMaxDynamicSharedMemorySize, GSM);
    cudaFuncSetAttribute(gemm_kernel<512, 512, 1>,  cudaFuncAttributeMaxDynamicSharedMemorySize, GSM);
    cudaFuncSetAttribute(gemm_kernel<512, 2048, 2>, cudaFuncAttributeMaxDynamicSharedMemorySize, GSM);
    cudaFuncSetAttribute(gemm_kernel<2048, 512, 3>, cudaFuncAttributeMaxDynamicSharedMemorySize, GSM);
    cudaFuncSetAttribute(tpose_kernel, cudaFuncAttributeMaxDynamicSharedMemorySize, TSM);

    const int PREP = W4 + 64 * 2450 + 1536;
    prep_kernel<<<(PREP + 255) / 256, 256>>>(qkv_w, proj_w, fc1_w, fc2_w, relb, qkv_b);
    ln1_kernel<<<128 * 14, 256>>>(x, ln1_w, ln1_b);
    gemm_kernel<512, 1536, 0><<<dim3(196, 12), 256, GSM>>>(nullptr, nullptr);
    attn_kernel<<<4096, 128>>>();
    gemm_kernel<512, 512, 1><<<dim3(196, 4), 256, GSM>>>(proj_b, gamma1);
    ln2_kernel<<<3136, 256>>>(ln2_w, ln2_b);
    gemm_kernel<512, 2048, 2><<<dim3(196, 16), 256, GSM>>>(fc1_b, nullptr);
    gemm_kernel<2048, 512, 3><<<dim3(196, 4), 256, GSM>>>(fc2_b, gamma2);
    tpose_kernel<<<512, 256, TSM>>>(out);
}

// round 17
// speedup vs baseline: 1.4989x; 1.0156x over previous
#include <cuda_runtime.h>
#include <cuda_bf16.h>
#include <cuda_fp16.h>
#include <cstdint>

// B=128, C=512, H=W=14, WIN=7, SHIFT=3, HEADS=16, HD=32, HID=2048
static constexpr int MT = 25088;  // B*H*W = B*nW*N

// ---- scratch (__device__ globals: allocation-free kernel_launch) ----
__device__ __align__(16) uint8_t  g_XW [(size_t)MT * 512];   // LN1 tokens, e4m3
__device__ __align__(16) float    g_XT [(size_t)MT * 512];   // x fp32 token-major
__device__ __align__(16) uint8_t  g_QK [(size_t)MT * 1024];  // q(0..511), k(512..1023) e4m3
__device__ __align__(16) __half   g_V  [(size_t)MT * 512];   // v f16
__device__ __align__(16) uint8_t  g_ATT[(size_t)MT * 512];   // e4m3
__device__ __align__(16) float    g_X1 [(size_t)MT * 512];   // running residual fp32
__device__ __align__(16) uint8_t  g_Z  [(size_t)MT * 512];   // e4m3
__device__ __align__(16) uint8_t  g_HB [(size_t)MT * 2048];  // e4m3
__device__ __align__(16) uint8_t g_QKVW[1536 * 512];
__device__ __align__(16) uint8_t g_PROJW[512 * 512];
__device__ __align__(16) uint8_t g_FC1W[2048 * 512];
__device__ __align__(16) uint8_t g_FC2W[512 * 2048];
__device__ float g_QKVB[1536];
__device__ float g_BM[64 * 49 * 50];    // [wl][head] combined bias+mask, stride-50 rows

// ---- PTX helpers ----
__device__ __forceinline__ void cp16(void* sm, const void* gm) {
    uint32_t s = (uint32_t)__cvta_generic_to_shared(sm);
    asm volatile("cp.async.cg.shared.global [%0], [%1], 16;\n" :: "r"(s), "l"(gm));
}
__device__ __forceinline__ void ldm4(uint32_t r[4], const void* p) {
    uint32_t a = (uint32_t)__cvta_generic_to_shared(p);
    asm volatile("ldmatrix.sync.aligned.m8n8.x4.shared.b16 {%0,%1,%2,%3}, [%4];\n"
                 : "=r"(r[0]), "=r"(r[1]), "=r"(r[2]), "=r"(r[3]) : "r"(a));
}
__device__ __forceinline__ void ldm4t(uint32_t r[4], const void* p) {
    uint32_t a = (uint32_t)__cvta_generic_to_shared(p);
    asm volatile("ldmatrix.sync.aligned.m8n8.x4.trans.shared.b16 {%0,%1,%2,%3}, [%4];\n"
                 : "=r"(r[0]), "=r"(r[1]), "=r"(r[2]), "=r"(r[3]) : "r"(a));
}
// f16-accumulate fp8 mma
__device__ __forceinline__ void mma_fp8h(uint32_t c[2], const uint32_t a[4], const uint32_t b[2]) {
    asm volatile("mma.sync.aligned.m16n8k32.row.col.f16.e4m3.e4m3.f16 "
                 "{%0,%1}, {%2,%3,%4,%5}, {%6,%7}, {%0,%1};\n"
                 : "+r"(c[0]), "+r"(c[1])
                 : "r"(a[0]), "r"(a[1]), "r"(a[2]), "r"(a[3]), "r"(b[0]), "r"(b[1]));
}
// f16 x f16 -> f16 mma (PV)
__device__ __forceinline__ void mma_h16(uint32_t c[2], const uint32_t a[4], const uint32_t b[2]) {
    asm volatile("mma.sync.aligned.m16n8k16.row.col.f16.f16.f16.f16 "
                 "{%0,%1}, {%2,%3,%4,%5}, {%6,%7}, {%0,%1};\n"
                 : "+r"(c[0]), "+r"(c[1])
                 : "r"(a[0]), "r"(a[1]), "r"(a[2]), "r"(a[3]), "r"(b[0]), "r"(b[1]));
}
__device__ __forceinline__ uint16_t pack8(float lo, float hi) {
    uint16_t r;
    asm("cvt.rn.satfinite.e4m3x2.f32 %0, %1, %2;" : "=h"(r) : "f"(hi), "f"(lo));
    return r;
}
__device__ __forceinline__ uint8_t fp8(float v) {
    return (uint8_t)(pack8(v, 0.f) & 0xFF);
}
__device__ __forceinline__ uint32_t packh(float a, float b) {
    __half2 t = __floats2half2_rn(a, b);
    return *reinterpret_cast<uint32_t*>(&t);
}

// ---- fused LN1 + prep: blocks [0,1792) do LN1, rest do weight/table prep ----
static constexpr int EW_ELEM = 512 * 6144;
static constexpr int W4 = EW_ELEM / 4;
static constexpr int PREP_ITEMS = W4 + 64 * 2450 + 1536;
static constexpr int PREP_BLKS = (PREP_ITEMS + 255) / 256;
static constexpr int LN1_BLKS = 128 * 14;

__global__ __launch_bounds__(256)
void ln1_prep_kernel(const float* __restrict__ xin, const float* __restrict__ w,
                     const float* __restrict__ bns,
                     const float* __restrict__ qkvw, const float* __restrict__ projw,
                     const float* __restrict__ fc1w, const float* __restrict__ fc2w,
                     const float* __restrict__ rel_bias, const float* __restrict__ qkvb) {
    __shared__ float tile[512 * 15];
    __shared__ float smu[14], srs[14];
    const int tid = threadIdx.x;

    if (blockIdx.x >= LN1_BLKS) {
        // ---- prep part ----
        int t = (blockIdx.x - LN1_BLKS) * 256 + tid;
        const int E0 = 1536 * 512, E1 = 512 * 512, E2 = 2048 * 512;
        if (t < W4) {
            int i = t * 4;
            float4 v;
            uint8_t* dst;
            if (i < E0) {
                v = *reinterpret_cast<const float4*>(qkvw + i);
                if (i < 512 * 512) {
                    v.x *= 0.17677669529663687f; v.y *= 0.17677669529663687f;
                    v.z *= 0.17677669529663687f; v.w *= 0.17677669529663687f;
                }
                dst = g_QKVW + i;
            } else if (i < E0 + E1) {
                v = *reinterpret_cast<const float4*>(projw + (i - E0));
                dst = g_PROJW + (i - E0);
            } else if (i < E0 + E1 + E2) {
                v = *reinterpret_cast<const float4*>(fc1w + (i - E0 - E1));
                dst = g_FC1W + (i - E0 - E1);
            } else {
                v = *reinterpret_cast<const float4*>(fc2w + (i - E0 - E1 - E2));
                dst = g_FC2W + (i - E0 - E1 - E2);
            }
            *reinterpret_cast<uint32_t*>(dst) =
                (uint32_t)pack8(v.x, v.y) | ((uint32_t)pack8(v.z, v.w) << 16);
        } else if (t < W4 + 64 * 2450) {
            int j = t - W4;
            int combo = j / 2450, e = j - combo * 2450;
            int wl = combo >> 4, head = combo & 15;
            int a = e / 50, b = e - a * 50;
            float v = 0.f;
            if (b < 49) {
                int ra = a / 7, ca = a - ra * 7, rb = b / 7, cb = b - rb * 7;
                v = rel_bias[((ra - rb + 6) * 13 + (ca - cb + 6)) * 16 + head];
                int wh = wl >> 1, ww = wl & 1;
                int ha = wh * 7 + ra, wa = ww * 7 + ca;
                int hb = wh * 7 + rb, wb = ww * 7 + cb;
                int ga = (ha < 7 ? 0 : (ha < 11 ? 1 : 2)) * 3 + (wa < 7 ? 0 : (wa < 11 ? 1 : 2));
                int gb = (hb < 7 ? 0 : (hb < 11 ? 1 : 2)) * 3 + (wb < 7 ? 0 : (wb < 11 ? 1 : 2));
                if (ga != gb) v -= 100.f;
            }
            g_BM[j] = v;
        } else if (t < PREP_ITEMS) {
            int j = t - W4 - 64 * 2450;
            g_QKVB[j] = qkvb[j] * (j < 512 ? 0.17677669529663687f : 1.f);
        }
        return;
    }

    // ---- LN1 part ----
    const int bb = blockIdx.x / 14, h = blockIdx.x - bb * 14;
    const float* xp = xin + (size_t)bb * 100352 + h * 14;

    for (int idx = tid; idx < 512 * 14; idx += 256) {
        int c = idx / 14, pp = idx - c * 14;
        tile[c * 15 + pp] = xp[(size_t)c * 196 + pp];
    }
    __syncthreads();

    const int warp = tid >> 5, lane = tid & 31;
    for (int pp = warp; pp < 14; pp += 8) {
        float s = 0.f, s2 = 0.f;
        for (int c = lane; c < 512; c += 32) {
            float v = tile[c * 15 + pp];
            s += v; s2 += v * v;
        }
        #pragma unroll
        for (int o = 16; o; o >>= 1) {
            s  += __shfl_xor_sync(0xffffffffu, s, o);
            s2 += __shfl_xor_sync(0xffffffffu, s2, o);
        }
        if (lane == 0) {
            float mu = s * (1.f / 512.f);
            float var = s2 * (1.f / 512.f) - mu * mu;
            smu[pp] = mu;
            srs[pp] = rsqrtf(var + 1e-5f);
        }
    }
    __syncthreads();

    for (int idx = tid; idx < 512 * 14; idx += 256) {
        int pp = idx >> 9, c = idx & 511;
        float raw = tile[c * 15 + pp];
        float v = (raw - smu[pp]) * srs[pp] * w[c] + bns[c];
        int hs = (h + 11) % 14, ws = (pp + 11) % 14;  // roll -SHIFT
        int m = bb * 196 + ((hs / 7) * 2 + ws / 7) * 49 + (hs % 7) * 7 + (ws % 7);
        g_XW[(size_t)m * 512 + c] = fp8(v);
        g_XT[(size_t)m * 512 + c] = raw;
    }
}

// ---- LN2: token-major g_X1 -> g_Z (e4m3) ----
__global__ __launch_bounds__(256)
void ln2_kernel(const float* __restrict__ w, const float* __restrict__ bns) {
    const int warp = threadIdx.x >> 5, lane = threadIdx.x & 31;
    const int m = blockIdx.x * 8 + warp;
    const float4* row = reinterpret_cast<const float4*>(g_X1 + (size_t)m * 512);
    float4 v[4];
    float s = 0.f, s2 = 0.f;
    #pragma unroll
    for (int j = 0; j < 4; ++j) {
        v[j] = row[lane + j * 32];
        s  += v[j].x + v[j].y + v[j].z + v[j].w;
        s2 += v[j].x * v[j].x + v[j].y * v[j].y + v[j].z * v[j].z + v[j].w * v[j].w;
    }
    #pragma unroll
    for (int o = 16; o; o >>= 1) {
        s  += __shfl_xor_sync(0xffffffffu, s, o);
        s2 += __shfl_xor_sync(0xffffffffu, s2, o);
    }
    const float mu = s * (1.f / 512.f);
    const float rs = rsqrtf(s2 * (1.f / 512.f) - mu * mu + 1e-5f);
    uint32_t* zrow = reinterpret_cast<uint32_t*>(g_Z + (size_t)m * 512);
    #pragma unroll
    for (int j = 0; j < 4; ++j) {
        const int c = (lane + j * 32) * 4;
        float o0 = (v[j].x - mu) * rs * w[c]     + bns[c];
        float o1 = (v[j].y - mu) * rs * w[c + 1] + bns[c + 1];
        float o2 = (v[j].z - mu) * rs * w[c + 2] + bns[c + 2];
        float o3 = (v[j].w - mu) * rs * w[c + 3] + bns[c + 3];
        zrow[lane + j * 32] = (uint32_t)pack8(o0, o1) | ((uint32_t)pack8(o2, o3) << 16);
    }
}

// ---- FP8 MMA GEMM, f16 accumulate (best known config).
// Block 128x128x128, 256 threads / 8 warps (2m x 4n), warp tile 64x32,
// 3-stage cp.async, 2 CTAs/SM, single sync per chunk.
static constexpr int LDSB = 144;                     // bytes per smem row
static constexpr int SA_T = 128 * LDSB;              // 18432
static constexpr int STG  = 2 * SA_T;                // 36864 per stage (A+B)
static constexpr int GSM  = 3 * STG;                 // 110592 B

template <int K, int N, int MODE>
__global__ __launch_bounds__(256, 2)
void gemm_kernel(const float* __restrict__ bias, const float* __restrict__ gamma) {
    const uint8_t* A;
    const uint8_t* Bw;
    if constexpr (MODE == 0)      { A = g_XW;  Bw = g_QKVW; }
    else if constexpr (MODE == 1) { A = g_ATT; Bw = g_PROJW; }
    else if constexpr (MODE == 2) { A = g_Z;   Bw = g_FC1W; }
    else                          { A = g_HB;  Bw = g_FC2W; }

    extern __shared__ __align__(16) uint8_t smem[];

    const int tid = threadIdx.x;
    const int lane = tid & 31, warp = tid >> 5;
    const int wm = warp & 1, wn = warp >> 1;          // 2m x 4n
    const int m0 = blockIdx.x * 128, n0 = blockIdx.y * 128;

    uint32_t acc[4][4][2];                            // f16x2 accumulators
    #pragma unroll
    for (int a = 0; a < 4; ++a)
        #pragma unroll
        for (int b = 0; b < 4; ++b) { acc[a][b][0] = 0u; acc[a][b][1] = 0u; }

    auto load_chunk = [&](int l) {
        uint8_t* stA = smem + (l % 3) * STG;
        uint8_t* stB = stA + SA_T;
        const int k0 = l * 128;
        #pragma unroll
        for (int i = 0; i < 4; ++i) {                  // A: 128 rows x 128 B
            int c = tid + i * 256;
            int row = c >> 3, cc = (c & 7) * 16;
            cp16(&stA[row * LDSB + cc], A + (size_t)(m0 + row) * K + k0 + cc);
        }
        #pragma unroll
        for (int i = 0; i < 4; ++i) {                  // B: 128 rows x 128 B
            int c = tid + i * 256;
            int row = c >> 3, cc = (c & 7) * 16;
            cp16(&stB[row * LDSB + cc], Bw + (size_t)(n0 + row) * K + k0 + cc);
        }
        asm volatile("cp.async.commit_group;\n");
    };

    const int KT = K / 128;
    load_chunk(0);
    if (KT > 1) load_chunk(1);

    #pragma unroll 1
    for (int c = 0; c < KT; ++c) {
        if (c + 1 < KT) asm volatile("cp.async.wait_group 1;\n");
        else            asm volatile("cp.async.wait_group 0;\n");
        __syncthreads();
        if (c + 2 < KT) load_chunk(c + 2);
        const uint8_t* stA = smem + (c % 3) * STG;
        const uint8_t* stB = stA + SA_T;
        #pragma unroll
        for (int ks = 0; ks < 4; ++ks) {               // 4 k-steps of k=32
            const int kcol = ks * 32 + (lane >> 4) * 16;   // byte offset
            uint32_t af[4][4], bf[4][2];
            #pragma unroll
            for (int tm = 0; tm < 4; ++tm)
                ldm4(af[tm], &stA[(wm * 64 + tm * 16 + (lane & 15)) * LDSB + kcol]);
            #pragma unroll
            for (int tb = 0; tb < 2; ++tb) {
                uint32_t r[4];
                ldm4(r, &stB[(wn * 32 + tb * 16 + (lane & 15)) * LDSB + kcol]);
                bf[2 * tb][0] = r[0]; bf[2 * tb][1] = r[2];
                bf[2 * tb + 1][0] = r[1]; bf[2 * tb + 1][1] = r[3];
            }
            #pragma unroll
            for (int tm = 0; tm < 4; ++tm)
                #pragma unroll
                for (int tn = 0; tn < 4; ++tn)
                    mma_fp8h(acc[tm][tn], af[tm], bf[tn]);
        }
    }

    // epilogue: row-major token-order; unpack f16x2 accumulators
    const int g = lane >> 2, qq = lane & 3;
    const bool isqk = (n0 < 1024);                     // MODE 0: q/k vs v region
    #pragma unroll
    for (int tm = 0; tm < 4; ++tm) {
        #pragma unroll
        for (int hh = 0; hh < 2; ++hh) {
            const int m = m0 + wm * 64 + tm * 16 + g + hh * 8;
            #pragma unroll
            for (int tn = 0; tn < 4; ++tn) {
                const int n = n0 + wn * 32 + tn * 8 + qq * 2;
                __half2 hv = *reinterpret_cast<const __half2*>(&acc[tm][tn][hh]);
                float v0 = __low2float(hv);
                float v1 = __high2float(hv);
                if constexpr (MODE == 0) {
                    v0 += g_QKVB[n]; v1 += g_QKVB[n + 1];
                    if (isqk) {
                        *reinterpret_cast<uint16_t*>(&g_QK[(size_t)m * 1024 + n]) = pack8(v0, v1);
                    } else {
                        *reinterpret_cast<uint32_t*>(&g_V[(size_t)m * 512 + (n - 1024)]) =
                            packh(v0, v1);
                    }
                } else if constexpr (MODE == 1) {
                    float2 xv = *reinterpret_cast<const float2*>(&g_XT[(size_t)m * 512 + n]);
                    float2 o;
                    o.x = xv.x + __ldg(&gamma[n])     * (v0 + __ldg(&bias[n]));
                    o.y = xv.y + __ldg(&gamma[n + 1]) * (v1 + __ldg(&bias[n + 1]));
                    *reinterpret_cast<float2*>(&g_X1[(size_t)m * 512 + n]) = o;
                } else if constexpr (MODE == 2) {
                    v0 += __ldg(&bias[n]); v1 += __ldg(&bias[n + 1]);
                    v0 *= normcdff(v0); v1 *= normcdff(v1);  // exact GELU
                    *reinterpret_cast<uint16_t*>(&g_HB[(size_t)m * 2048 + n]) = pack8(v0, v1);
                } else {
                    float2 xv = *reinterpret_cast<const float2*>(&g_X1[(size_t)m * 512 + n]);
                    float2 o;
                    o.x = xv.x + __ldg(&gamma[n])     * (v0 + __ldg(&bias[n]));
                    o.y = xv.y + __ldg(&gamma[n + 1]) * (v1 + __ldg(&bias[n + 1]));
                    *reinterpret_cast<float2*>(&g_X1[(size_t)m * 512 + n]) = o;  // in-place
                }
            }
        }
    }
}

// ---- final transpose: g_X1 token-major (window order) -> d_out NCHW fp32 ----
__global__ __launch_bounds__(256)
void tpose_kernel(float* __restrict__ out) {
    extern __shared__ float ts[];      // [196][129]
    __shared__ int ptab[196];
    const int b = blockIdx.x >> 2, cc = (blockIdx.x & 3) * 128;
    const int tid = threadIdx.x;
    if (tid < 196) {
        int wl = tid / 49, t = tid - wl * 49;
        int hs = (wl >> 1) * 7 + t / 7, ws = (wl & 1) * 7 + t % 7;
        ptab[tid] = ((hs + 3) % 14) * 14 + ((ws + 3) % 14);
    }
    __syncthreads();
    for (int i = tid; i < 196 * 128; i += 256) {
        int ml = i >> 7, c = i & 127;
        ts[ptab[ml] * 129 + c] = g_X1[((size_t)b * 196 + ml) * 512 + cc + c];
    }
    __syncthreads();
    for (int i = tid; i < 128 * 196; i += 256) {
        int c = i / 196, p = i - c * 196;
        out[(size_t)b * 100352 + (size_t)(cc + c) * 196 + p] = ts[p * 129 + c];
    }
}

// ---- attention: 2 (window,head) tasks / 128-thread block.
// S = Q K^T fp8->f16 acc; softmax fp32 transient, P packed f16; P·V f16 mma
// with f16 acc. Low register footprint -> high occupancy.
__global__ __launch_bounds__(128) void attn_kernel() {
    __shared__ __align__(16) uint8_t sQ8[2][64 * 48];
    __shared__ __align__(16) uint8_t sK8[2][64 * 48];
    __shared__ __align__(16) __half  sV [2][64 * 40];

    const int tid = threadIdx.x, lane = tid & 31, warp = tid >> 5;
    const int task0 = blockIdx.x * 2;

    for (int i = tid; i < 2 * 2 * 49 * 2; i += 128) {
        int tloc = i / 196, rem = i - tloc * 196;
        int tensor = rem / 98, rr = rem - tensor * 98;
        int row = rr >> 1, chunk = rr & 1;
        int task = task0 + tloc;
        int head = task & 15, wbi = task >> 4;
        int mbase = (wbi >> 2) * 196 + (wbi & 3) * 49;
        const uint4* src = reinterpret_cast<const uint4*>(
            &g_QK[(size_t)(mbase + row) * 1024 + tensor * 512 + head * 32 + chunk * 16]);
        uint8_t* dst = (tensor == 0 ? sQ8 : sK8)[tloc];
        *reinterpret_cast<uint4*>(&dst[row * 48 + chunk * 16]) = *src;
    }
    for (int i = tid; i < 2 * 49 * 4; i += 128) {
        int tloc = i / 196, rr = i - tloc * 196;
        int row = rr >> 2, chunk = rr & 3;
        int task = task0 + tloc;
        int head = task & 15, wbi = task >> 4;
        int mbase = (wbi >> 2) * 196 + (wbi & 3) * 49;
        const uint4* src = reinterpret_cast<const uint4*>(
            &g_V[(size_t)(mbase + row) * 512 + head * 32 + chunk * 8]);
        *reinterpret_cast<uint4*>(&sV[tloc][row * 40 + chunk * 8]) = *src;
    }
    for (int i = tid; i < 2 * 15 * 3; i += 128) {
        int tloc = i / 45, rr = i - tloc * 45;
        int row = 49 + rr / 3, chunk = rr % 3;
        *reinterpret_cast<uint4*>(&sQ8[tloc][row * 48 + chunk * 16]) = make_uint4(0, 0, 0, 0);
        *reinterpret_cast<uint4*>(&sK8[tloc][row * 48 + chunk * 16]) = make_uint4(0, 0, 0, 0);
    }
    for (int i = tid; i < 2 * 15 * 5; i += 128) {
        int tloc = i / 75, rr = i - tloc * 75;
        int row = 49 + rr / 5, chunk = rr % 5;
        *reinterpret_cast<uint4*>(&sV[tloc][row * 40 + chunk * 8]) = make_uint4(0, 0, 0, 0);
    }
    __syncthreads();

    const int tloc = warp >> 1, mhalf = warp & 1;
    const int task = task0 + tloc;
    const int head = task & 15, wbi = task >> 4;
    const int wl = wbi & 3;
    const int mbase = (wbi >> 2) * 196 + wl * 49;
    const int g = lane >> 2, qq = lane & 3;
    const uint8_t* Qs = sQ8[tloc];
    const uint8_t* Ks = sK8[tloc];
    const __half* Vs = sV[tloc];

    // ---- S = Q K^T : single fp8 k32 step, f16 accumulators ----
    uint32_t sh[2][8][2];
    #pragma unroll
    for (int a = 0; a < 2; ++a)
        #pragma unroll
        for (int b = 0; b < 8; ++b) { sh[a][b][0] = 0u; sh[a][b][1] = 0u; }

    {
        const int kcol = (lane >> 4) * 16;
        uint32_t af[2][4], bf[8][2];
        #pragma unroll
        for (int tm = 0; tm < 2; ++tm)
            ldm4(af[tm], &Qs[(mhalf * 32 + tm * 16 + (lane & 15)) * 48 + kcol]);
        #pragma unroll
        for (int tb = 0; tb < 4; ++tb) {
            uint32_t r[4];
            ldm4(r, &Ks[(tb * 16 + (lane & 15)) * 48 + kcol]);
            bf[2 * tb][0] = r[0]; bf[2 * tb][1] = r[2];
            bf[2 * tb + 1][0] = r[1]; bf[2 * tb + 1][1] = r[3];
        }
        #pragma unroll
        for (int tm = 0; tm < 2; ++tm)
            #pragma unroll
            for (int nf = 0; nf < 8; ++nf)
                mma_fp8h(sh[tm][nf], af[tm], bf[nf]);
    }

    // ---- bias+mask add (f16) + softmax (fp32 transient), P packed f16 ----
    const float* bt = g_BM + (wl * 16 + head) * 2450;
    float rsum[2][2];
    #pragma unroll
    for (int tm = 0; tm < 2; ++tm) {
        #pragma unroll
        for (int rr = 0; rr < 2; ++rr) {
            const int row = mhalf * 32 + tm * 16 + g + rr * 8;
            if (row < 49) {
                #pragma unroll
                for (int nf = 0; nf < 8; ++nf) {
                    const int col = nf * 8 + 2 * qq;
                    __half2 bm;
                    if (col < 49) {
                        float2 b2 = *reinterpret_cast<const float2*>(&bt[row * 50 + col]);
                        if (col + 1 >= 49) b2.y = -30000.f;
                        bm = __floats2half2_rn(b2.x, b2.y);
                    } else {
                        bm = __floats2half2_rn(-30000.f, -30000.f);
                    }
                    __half2 cur = *reinterpret_cast<const __half2*>(&sh[tm][nf][rr]);
                    __half2 upd = __hadd2(cur, bm);
                    sh[tm][nf][rr] = *reinterpret_cast<const uint32_t*>(&upd);
                }
            }
            float mx = -1e30f;
            #pragma unroll
            for (int nf = 0; nf < 8; ++nf) {
                float2 f = __half22float2(*reinterpret_cast<const __half2*>(&sh[tm][nf][rr]));
                mx = fmaxf(mx, fmaxf(f.x, f.y));
            }
            mx = fmaxf(mx, __shfl_xor_sync(0xffffffffu, mx, 1));
            mx = fmaxf(mx, __shfl_xor_sync(0xffffffffu, mx, 2));
            float s = 0.f;
            #pragma unroll
            for (int nf = 0; nf < 8; ++nf) {
                float2 f = __half22float2(*reinterpret_cast<const __half2*>(&sh[tm][nf][rr]));
                float p0 = __expf(f.x - mx);
                float p1 = __expf(f.y - mx);
                s += p0 + p1;
                sh[tm][nf][rr] = packh(p0, p1);
            }
            s += __shfl_xor_sync(0xffffffffu, s, 1);
            s += __shfl_xor_sync(0xffffffffu, s, 2);
            rsum[tm][rr] = s;
        }
    }

    // ---- D = P V : f16 x f16 -> f16, K=64 (4 k16 steps) ----
    uint32_t dacc[2][4][2];
    #pragma unroll
    for (int a = 0; a < 2; ++a)
        #pragma unroll
        for (int b = 0; b < 4; ++b) { dacc[a][b][0] = 0u; dacc[a][b][1] = 0u; }

    #pragma unroll
    for (int kk = 0; kk < 4; ++kk) {
        uint32_t pa[2][4];
        #pragma unroll
        for (int tm = 0; tm < 2; ++tm) {
            pa[tm][0] = sh[tm][2 * kk][0];
            pa[tm][1] = sh[tm][2 * kk][1];
            pa[tm][2] = sh[tm][2 * kk + 1][0];
            pa[tm][3] = sh[tm][2 * kk + 1][1];
        }
        uint32_t bv[4][2];
        #pragma unroll
        for (int half = 0; half < 2; ++half) {
            uint32_t r[4];
            ldm4t(r, &Vs[(kk * 16 + (lane & 15)) * 40 + half * 16 + (lane >> 4) * 8]);
            bv[half * 2 + 0][0] = r[0]; bv[half * 2 + 0][1] = r[1];
            bv[half * 2 + 1][0] = r[2]; bv[half * 2 + 1][1] = r[3];
        }
        #pragma unroll
        for (int tm = 0; tm < 2; ++tm)
            #pragma unroll
            for (int tn = 0; tn < 4; ++tn)
                mma_h16(dacc[tm][tn], pa[tm], bv[tn]);
    }

    #pragma unroll
    for (int tm = 0; tm < 2; ++tm) {
        #pragma unroll
        for (int rr = 0; rr < 2; ++rr) {
            const int row = mhalf * 32 + tm * 16 + g + rr * 8;
            if (row < 49) {
                const float inv = 1.f / rsum[tm][rr];
                #pragma unroll
                for (int tn = 0; tn < 4; ++tn) {
                    const int col = tn * 8 + 2 * qq;
                    float2 dv = __half22float2(
                        *reinterpret_cast<const __half2*>(&dacc[tm][tn][rr]));
                    *reinterpret_cast<uint16_t*>(
                        &g_ATT[(size_t)(mbase + row) * 512 + head * 32 + col]) =
                        pack8(dv.x * inv, dv.y * inv);
                }
            }
        }
    }
}

extern "C" void kernel_launch(void* const* d_in, const int* in_sizes, int n_in,
                              void* d_out, int out_size) {
    const float* x      = (const float*)d_in[0];
    const float* ln1_w  = (const float*)d_in[1];
    const float* ln1_b  = (const float*)d_in[2];
    const float* qkv_w  = (const float*)d_in[3];
    const float* qkv_b  = (const float*)d_in[4];
    const float* relb   = (const float*)d_in[5];
    const float* proj_w = (const float*)d_in[6];
    const float* proj_b = (const float*)d_in[7];
    const float* gamma1 = (const float*)d_in[8];
    const float* ln2_w  = (const float*)d_in[9];
    const float* ln2_b  = (const float*)d_in[10];
    const float* fc1_w  = (const float*)d_in[11];
    const float* fc1_b  = (const float*)d_in[12];
    const float* fc2_w  = (const float*)d_in[13];
    const float* fc2_b  = (const float*)d_in[14];
    const float* gamma2 = (const float*)d_in[15];
    float* out = (float*)d_out;

    const int TSM = 196 * 129 * 4;
    cudaFuncSetAttribute(gemm_kernel<512, 1536, 0>, cudaFuncAttributeMaxDynamicSharedMemorySize, GSM);
    cudaFuncSetAttribute(gemm_kernel<512, 512, 1>,  cudaFuncAttributeMaxDynamicSharedMemorySize, GSM);
    cudaFuncSetAttribute(gemm_kernel<512, 2048, 2>, cudaFuncAttributeMaxDynamicSharedMemorySize, GSM);
    cudaFuncSetAttribute(gemm_kernel<2048, 512, 3>, cudaFuncAttributeMaxDynamicSharedMemorySize, GSM);
    cudaFuncSetAttribute(tpose_kernel, cudaFuncAttributeMaxDynamicSharedMemorySize, TSM);

    ln1_prep_kernel<<<LN1_BLKS + PREP_BLKS, 256>>>(x, ln1_w, ln1_b,
                                                   qkv_w, proj_w, fc1_w, fc2_w, relb, qkv_b);
    gemm_kernel<512, 1536, 0><<<dim3(196, 12), 256, GSM>>>(nullptr, nullptr);
    attn_kernel<<<4096, 128>>>();
    gemm_kernel<512, 512, 1><<<dim3(196, 4), 256, GSM>>>(proj_b, gamma1);
    ln2_kernel<<<3136, 256>>>(ln2_w, ln2_b);
    gemm_kernel<512, 2048, 2><<<dim3(196, 16), 256, GSM>>>(fc1_b, nullptr);
    gemm_kernel<2048, 512, 3><<<dim3(196, 4), 256, GSM>>>(fc2_b, gamma2);
    tpose_kernel<<<512, 256, TSM>>>(out);
}